// round 11
// baseline (speedup 1.0000x reference)
#include <cuda_runtime.h>

#define R 16
#define A 8
#define THREADS 256
#define ROWS_PER_CTA (2 * THREADS)

__device__ __forceinline__ float ex2f(float x) {
    float r;
    asm("ex2.approx.f32 %0, %1;" : "=f"(r) : "f"(x));
    return r;
}

__global__ __launch_bounds__(THREADS)   // no min-blocks cap: let ptxas pick regs, no spills
void t2fls_kernel(const float* __restrict__ x_in,
                  const float* __restrict__ W,
                  const float* __restrict__ c1,
                  const float* __restrict__ c2,
                  float* __restrict__ out, int n)
{
    // d = U-L per (rule, row). Column is touched only by the owning thread.
    __shared__ float shD[R][ROWS_PER_CTA];                  // 32 KB
    // Coefficients in c1-sorted rule order, natural feature order (float4-loadable).
    __shared__ __align__(16) float sh_nm[R][A];             // negated centers
    __shared__ __align__(16) float sh_gb[R][A];             // -0.5*log2(e)/smax^2 (U)
    __shared__ __align__(16) float sh_gs[R][A];             // -0.5*log2(e)/smin^2 (L)
    // Per sorted slot j: (c1s[j], c2s[j], as_float(q[j]*ROWS_PER_CTA), c2[p1[j]])
    __shared__ float4 shScan[R];
    __shared__ int   sh_p1[R], sh_inv1[R], sh_p2[R];
    __shared__ float sh_c1s[R], sh_c2s[R];

    int t = threadIdx.x;

    // ---- Phase A: parallel rank-sort of c1 (threads 0..15) and c2 (threads 16..31) ----
    if (t < R) {
        float cj = c1[t];
        int rank = 0;
        #pragma unroll
        for (int i = 0; i < R; i++) {
            float ci = c1[i];
            rank += (ci < cj) || (ci == cj && i < t);   // stable
        }
        sh_p1[rank] = t;
        sh_inv1[t] = rank;
        sh_c1s[rank] = cj;
    } else if (t < 2 * R) {
        int j = t - R;
        float cj = c2[j];
        int rank = 0;
        #pragma unroll
        for (int i = 0; i < R; i++) {
            float ci = c2[i];
            rank += (ci < cj) || (ci == cj && i < j);   // stable
        }
        sh_p2[rank] = j;
        sh_c2s[rank] = cj;
    }
    __syncthreads();

    // ---- Phase B: coefficient transform into c1-sorted layout ----
    if (t < R * A) {
        int r = t >> 3, a = t & 7;
        // offsets = A*r + a == t ; m = W[t], s1 = W[t+1], s2 = W[t+2]
        float m  = W[t];
        float s1 = W[t + 1];
        float s2 = W[t + 2];
        float smax = fmaxf(s1, s2);
        float smin = fminf(s1, s2);
        const float k = -0.5f * 1.44269504088896340736f;  // -0.5 * log2(e)
        int slot = sh_inv1[r];
        sh_nm[slot][a] = -m;
        sh_gb[slot][a] = k / (smax * smax);
        sh_gs[slot][a] = k / (smin * smin);
    }
    if (t < R) {
        int q = sh_inv1[sh_p2[t]];   // slot (in c1-order storage) of rule p2[t]
        shScan[t] = make_float4(sh_c1s[t], sh_c2s[t],
                                __int_as_float(q * ROWS_PER_CTA),
                                c2[sh_p1[t]]);           // c2 value of rule at c1-slot t
    }
    __syncthreads();

    int base = blockIdx.x * ROWS_PER_CTA;
    int ia = base + t;
    int ib = base + t + THREADS;
    // Clamp load indices (stores are guarded); keeps the hot path branch-free.
    int la = ia < n ? ia : (n - 1);
    int lb = ib < n ? ib : (n - 1);

    // Load the two 8-feature rows with float4s.
    const float4* xpa = (const float4*)(x_in + (size_t)la * A);
    const float4* xpb = (const float4*)(x_in + (size_t)lb * A);
    float4 xa0 = xpa[0], xa1 = xpa[1];
    float4 xb0 = xpb[0], xb1 = xpb[1];

    float s0a = 0.f, t0a = 0.f, s0ra = 0.f, t0ra = 0.f;
    float s0b = 0.f, t0b = 0.f, s0rb = 0.f, t0rb = 0.f;

    #pragma unroll 2
    for (int j = 0; j < R; j++) {
        float4 nm0 = *(const float4*)&sh_nm[j][0];
        float4 nm1 = *(const float4*)&sh_nm[j][4];
        float4 gb0 = *(const float4*)&sh_gb[j][0];
        float4 gb1 = *(const float4*)&sh_gb[j][4];
        float4 gs0 = *(const float4*)&sh_gs[j][0];
        float4 gs1 = *(const float4*)&sh_gs[j][4];

        float sua = 0.f, sla = 0.f, sub = 0.f, slb = 0.f, d, e;
        // Row a
        d = xa0.x + nm0.x; e = d * d; sua = fmaf(e, gb0.x, sua); sla = fmaf(e, gs0.x, sla);
        d = xa0.y + nm0.y; e = d * d; sua = fmaf(e, gb0.y, sua); sla = fmaf(e, gs0.y, sla);
        d = xa0.z + nm0.z; e = d * d; sua = fmaf(e, gb0.z, sua); sla = fmaf(e, gs0.z, sla);
        d = xa0.w + nm0.w; e = d * d; sua = fmaf(e, gb0.w, sua); sla = fmaf(e, gs0.w, sla);
        d = xa1.x + nm1.x; e = d * d; sua = fmaf(e, gb1.x, sua); sla = fmaf(e, gs1.x, sla);
        d = xa1.y + nm1.y; e = d * d; sua = fmaf(e, gb1.y, sua); sla = fmaf(e, gs1.y, sla);
        d = xa1.z + nm1.z; e = d * d; sua = fmaf(e, gb1.z, sua); sla = fmaf(e, gs1.z, sla);
        d = xa1.w + nm1.w; e = d * d; sua = fmaf(e, gb1.w, sua); sla = fmaf(e, gs1.w, sla);
        // Row b (reuses the same coefficient registers)
        d = xb0.x + nm0.x; e = d * d; sub = fmaf(e, gb0.x, sub); slb = fmaf(e, gs0.x, slb);
        d = xb0.y + nm0.y; e = d * d; sub = fmaf(e, gb0.y, sub); slb = fmaf(e, gs0.y, slb);
        d = xb0.z + nm0.z; e = d * d; sub = fmaf(e, gb0.z, sub); slb = fmaf(e, gs0.z, slb);
        d = xb0.w + nm0.w; e = d * d; sub = fmaf(e, gb0.w, sub); slb = fmaf(e, gs0.w, slb);
        d = xb1.x + nm1.x; e = d * d; sub = fmaf(e, gb1.x, sub); slb = fmaf(e, gs1.x, slb);
        d = xb1.y + nm1.y; e = d * d; sub = fmaf(e, gb1.y, sub); slb = fmaf(e, gs1.y, slb);
        d = xb1.z + nm1.z; e = d * d; sub = fmaf(e, gb1.z, sub); slb = fmaf(e, gs1.z, slb);
        d = xb1.w + nm1.w; e = d * d; sub = fmaf(e, gb1.w, sub); slb = fmaf(e, gs1.w, slb);

        float Ua = ex2f(sua), La = ex2f(sla);
        float Ub = ex2f(sub), Lb = ex2f(slb);

        float4 sc = shScan[j];
        s0a  = fmaf(sc.x, La, s0a);   t0a  += La;
        s0ra = fmaf(sc.w, Ua, s0ra);  t0ra += Ua;
        s0b  = fmaf(sc.x, Lb, s0b);   t0b  += Lb;
        s0rb = fmaf(sc.w, Ub, s0rb);  t0rb += Ub;
        shD[j][t] = Ua - La;
        shD[j][t + THREADS] = Ub - Lb;
    }

    float lefta  = __fdividef(s0a,  t0a);
    float righta = __fdividef(s0ra, t0ra);
    float leftb  = __fdividef(s0b,  t0b);
    float rightb = __fdividef(s0rb, t0rb);

    float csa = 0.f, cta = 0.f, csra = 0.f, ctra = 0.f;
    float csb = 0.f, ctb = 0.f, csrb = 0.f, ctrb = 0.f;
    const float* shDf = &shD[0][0];
    #pragma unroll
    for (int j = 0; j < R; j++) {
        float4 sc = shScan[j];
        // Left scan: storage is already c1-sorted -> compile-time offsets.
        float dja = shD[j][t];
        float djb = shD[j][t + THREADS];
        csa = fmaf(sc.x, dja, csa);  cta += dja;
        csb = fmaf(sc.x, djb, csb);  ctb += djb;
        lefta = fminf(lefta, __fdividef(s0a + csa, t0a + cta));
        leftb = fminf(leftb, __fdividef(s0b + csb, t0b + ctb));
        // Right scan: c2-sorted order via runtime slot offset (same-thread column).
        int off = __float_as_int(sc.z);
        float dqa = shDf[off + t];
        float dqb = shDf[off + t + THREADS];
        csra = fmaf(sc.y, dqa, csra);  ctra += dqa;
        csrb = fmaf(sc.y, dqb, csrb);  ctrb += dqb;
        // dr = L - U = -dq  =>  ratio = (s0r - csr)/(t0r - ctr)
        righta = fmaxf(righta, __fdividef(s0ra - csra, t0ra - ctra));
        rightb = fmaxf(rightb, __fdividef(s0rb - csrb, t0rb - ctrb));
    }

    if (ia < n) out[ia] = 0.5f * (lefta + righta);
    if (ib < n) out[ib] = 0.5f * (leftb + rightb);
}

extern "C" void kernel_launch(void* const* d_in, const int* in_sizes, int n_in,
                              void* d_out, int out_size) {
    const float* x  = (const float*)d_in[0];
    const float* W  = (const float*)d_in[1];
    const float* c1 = (const float*)d_in[2];
    const float* c2 = (const float*)d_in[3];
    float* out = (float*)d_out;
    int n = out_size;  // one output per row

    int blocks = (n + ROWS_PER_CTA - 1) / ROWS_PER_CTA;
    t2fls_kernel<<<blocks, THREADS>>>(x, W, c1, c2, out, n);
}